// round 9
// baseline (speedup 1.0000x reference)
#include <cuda_runtime.h>
#include <cstdint>

// Voxels_40518721470753 — R4 shell (256-thread blocks, TMA in/out, branchless
// predicated gathers) + paired-tile pipelining + tanh-based sigmoid.
// out[0:3N] = sigmoid(rgb) ([N,3]); out[3N:4N] = relu(dens*10)
// idx(v) = ((int)floorf(v*128+64) - 1) & 127 ; !cond -> rgb 0.5, dens 0

#define NB        128
#define TPB       256
#define PPB       1024                 // points per tile
#define X_BYTES   (PPB * 3 * 4)        // 12288
#define D_BYTES   (PPB * 4)            // 4096

__device__ __forceinline__ uint32_t smem_u32(const void* p) {
    return (uint32_t)__cvta_generic_to_shared(p);
}
__device__ __forceinline__ float fast_sigmoid(float v) {
    // sigmoid(v) = 0.5*tanh(v/2) + 0.5  (1 MUFU instead of EX2+RCP)
    float t, h = 0.5f * v;
    asm("tanh.approx.f32 %0, %1;" : "=f"(t) : "f"(h));
    return fmaf(0.5f, t, 0.5f);
}
__device__ __forceinline__ int to_idx(float v) {
    return (((int)floorf(v * 128.0f + 64.0f)) - 1) & (NB - 1);
}
__device__ __forceinline__ void mbar_wait0(uint32_t mb) {
    asm volatile(
        "{\n\t"
        ".reg .pred P;\n\t"
        "W%=:\n\t"
        "mbarrier.try_wait.parity.shared::cta.b64 P, [%0], 0, 10000000;\n\t"
        "@!P bra W%=;\n\t"
        "}"
        :: "r"(mb) : "memory");
}

struct Smem {
    __align__(128) float4 sX[2][PPB * 3 / 4];  // 2 x 12 KB: X tiles -> rgb out
    __align__(128) float4 sD[2][PPB / 4];      // 2 x 4 KB dens
    __align__(8)   uint64_t mbar[2];
};

__global__ __launch_bounds__(TPB) void voxels_kernel(
    const float*  __restrict__ Xg,        // [N,3]
    const float4* __restrict__ vox,       // [128^3] float4
    float*        __restrict__ rgb_out,   // 3N floats
    float*        __restrict__ dens_out)  // N floats
{
    __shared__ Smem sm;

    const int tid = threadIdx.x;
    const long long base0 = (long long)blockIdx.x * (2 * PPB);

    if (tid < 2) {
        asm volatile("mbarrier.init.shared::cta.b64 [%0], 1;"
                     :: "r"(smem_u32(&sm.mbar[tid])) : "memory");
    }
    __syncthreads();

    // ---- issue both X tile loads immediately ----
    if (tid == 0) {
#pragma unroll
        for (int s = 0; s < 2; s++) {
            uint32_t mb = smem_u32(&sm.mbar[s]);
            asm volatile("mbarrier.arrive.expect_tx.shared::cta.b64 _, [%0], %1;"
                         :: "r"(mb), "n"(X_BYTES) : "memory");
            asm volatile(
                "cp.async.bulk.shared::cluster.global.mbarrier::complete_tx::bytes "
                "[%0], [%1], %2, [%3];"
                :: "r"(smem_u32(&sm.sX[s][0])),
                   "l"(Xg + (base0 + (long long)s * PPB) * 3),
                   "n"(X_BYTES), "r"(mb)
                : "memory");
        }
    }

#pragma unroll
    for (int s = 0; s < 2; s++) {
        mbar_wait0(smem_u32(&sm.mbar[s]));

        // ---- per-thread compute: points 4*tid .. 4*tid+3 of tile s ----
        float4 a = sm.sX[s][3 * tid + 0];
        float4 b = sm.sX[s][3 * tid + 1];
        float4 c = sm.sX[s][3 * tid + 2];

        float px[4] = {a.x, a.w, b.z, c.y};
        float py[4] = {a.y, b.x, b.w, c.z};
        float pz[4] = {a.z, b.y, c.x, c.w};

        int  idx[4];
        bool cd[4];
#pragma unroll
        for (int k = 0; k < 4; k++) {
            float x = px[k], y = py[k], z = pz[k];
            cd[k]  = (fabsf(x) < 0.5f) & (fabsf(y) < 0.5f) & (fabsf(z) < 0.5f);
            idx[k] = (to_idx(x) * NB + to_idx(y)) * NB + to_idx(z);
        }

        float4 v[4];
#pragma unroll
        for (int k = 0; k < 4; k++) {
            float4 g = make_float4(0.f, 0.f, 0.f, 0.f);
            if (cd[k]) g = __ldg(&vox[idx[k]]);   // predicated LDG.E.128
            v[k] = g;
        }

        float ro[12], dv[4];
#pragma unroll
        for (int k = 0; k < 4; k++) {
            ro[3 * k + 0] = fast_sigmoid(v[k].x);
            ro[3 * k + 1] = fast_sigmoid(v[k].y);
            ro[3 * k + 2] = fast_sigmoid(v[k].z);
            dv[k] = fmaxf(v[k].w * 10.0f, 0.0f);
        }

        // overwrite own X slots with rgb results (no cross-thread hazard)
        sm.sX[s][3 * tid + 0] = make_float4(ro[0], ro[1], ro[2],  ro[3]);
        sm.sX[s][3 * tid + 1] = make_float4(ro[4], ro[5], ro[6],  ro[7]);
        sm.sX[s][3 * tid + 2] = make_float4(ro[8], ro[9], ro[10], ro[11]);
        sm.sD[s][tid]         = make_float4(dv[0], dv[1], dv[2],  dv[3]);
        __syncthreads();

        // ---- fire-and-forget bulk stores for tile s ----
        if (tid == 0) {
            const long long base = base0 + (long long)s * PPB;
            asm volatile("fence.proxy.async.shared::cta;" ::: "memory");
            asm volatile(
                "cp.async.bulk.global.shared::cta.bulk_group [%0], [%1], %2;"
                :: "l"(rgb_out + base * 3), "r"(smem_u32(&sm.sX[s][0])),
                   "n"(X_BYTES) : "memory");
            asm volatile(
                "cp.async.bulk.global.shared::cta.bulk_group [%0], [%1], %2;"
                :: "l"(dens_out + base), "r"(smem_u32(&sm.sD[s][0])),
                   "n"(D_BYTES) : "memory");
            asm volatile("cp.async.bulk.commit_group;" ::: "memory");
        }
        // no per-tile drain: distinct output buffers per s
    }

    // drain both store groups before smem is released
    if (tid == 0)
        asm volatile("cp.async.bulk.wait_group.read 0;" ::: "memory");
}

extern "C" void kernel_launch(void* const* d_in, const int* in_sizes, int n_in,
                              void* d_out, int out_size)
{
    const float* X      = (const float*)d_in[0];   // [N,3]
    const float* voxels = (const float*)d_in[1];   // [128,128,128,4]

    int n = in_sizes[0] / 3;                       // 8388608
    int nblocks = n / (2 * PPB);                   // 4096 blocks x 2 tiles

    float* out      = (float*)d_out;
    float* rgb_out  = out;                         // first 3N floats
    float* dens_out = out + 3LL * n;               // last  N floats

    voxels_kernel<<<nblocks, TPB>>>(
        X, (const float4*)voxels, rgb_out, dens_out);
}

// round 10
// speedup vs baseline: 1.5430x; 1.5430x over previous
#include <cuda_runtime.h>
#include <cstdint>

// Voxels_40518721470753 — R4 shell (grid 8192, 1024-pt tile, TMA in/out,
// branchless predicated gathers) with TPB=128: each thread runs TWO 4-point
// groups -> 8 gathers in flight per thread. tanh-based sigmoid (1 MUFU).
// out[0:3N] = sigmoid(rgb) ([N,3]); out[3N:4N] = relu(dens*10)
// idx(v) = ((int)floorf(v*128+64) - 1) & 127 ; !cond -> rgb 0.5, dens 0

#define NB        128
#define TPB       128
#define PPB       1024                 // points per block
#define X_BYTES   (PPB * 3 * 4)        // 12288
#define D_BYTES   (PPB * 4)            // 4096

__device__ __forceinline__ uint32_t smem_u32(const void* p) {
    return (uint32_t)__cvta_generic_to_shared(p);
}
__device__ __forceinline__ float fast_sigmoid(float v) {
    // sigmoid(v) = 0.5*tanh(v/2) + 0.5 (verified rel_err ~5e-7 in R8)
    float t, h = 0.5f * v;
    asm("tanh.approx.f32 %0, %1;" : "=f"(t) : "f"(h));
    return fmaf(0.5f, t, 0.5f);
}
__device__ __forceinline__ int to_idx(float v) {
    return (((int)floorf(v * 128.0f + 64.0f)) - 1) & (NB - 1);
}

__global__ __launch_bounds__(TPB, 10) void voxels_kernel(
    const float*  __restrict__ Xg,        // [N,3]
    const float4* __restrict__ vox,       // [128^3] float4
    float*        __restrict__ rgb_out,   // 3N floats
    float*        __restrict__ dens_out)  // N floats
{
    __shared__ __align__(128) float4 s_buf[PPB * 3 / 4];  // 12 KB: X -> rgb
    __shared__ __align__(128) float4 s_dens[PPB / 4];     // 4 KB
    __shared__ __align__(8)   uint64_t mbar;

    const int tid = threadIdx.x;
    const long long base = (long long)blockIdx.x * PPB;

    const uint32_t mb = smem_u32(&mbar);
    if (tid == 0) {
        asm volatile("mbarrier.init.shared::cta.b64 [%0], 1;" :: "r"(mb) : "memory");
    }
    __syncthreads();

    // ---- TMA bulk load of this block's X tile ----
    if (tid == 0) {
        asm volatile("mbarrier.arrive.expect_tx.shared::cta.b64 _, [%0], %1;"
                     :: "r"(mb), "n"(X_BYTES) : "memory");
        asm volatile(
            "cp.async.bulk.shared::cluster.global.mbarrier::complete_tx::bytes "
            "[%0], [%1], %2, [%3];"
            :: "r"(smem_u32(s_buf)), "l"(Xg + base * 3), "n"(X_BYTES), "r"(mb)
            : "memory");
    }
    asm volatile(
        "{\n\t"
        ".reg .pred P;\n\t"
        "W%=:\n\t"
        "mbarrier.try_wait.parity.shared::cta.b64 P, [%0], 0, 10000000;\n\t"
        "@!P bra W%=;\n\t"
        "}"
        :: "r"(mb) : "memory");

    // ---- two 4-point groups per thread: slots g0 = tid, g1 = tid + 128 ----
    // Each group's 3 float4 reads are the R4 conflict-free 48B-stride pattern.
    int  idx[8];
    bool cd[8];
    float4 v[8];

#pragma unroll
    for (int grp = 0; grp < 2; grp++) {
        const int g = tid + grp * TPB;
        float4 a = s_buf[3 * g + 0];
        float4 b = s_buf[3 * g + 1];
        float4 c = s_buf[3 * g + 2];

        float px[4] = {a.x, a.w, b.z, c.y};
        float py[4] = {a.y, b.x, b.w, c.z};
        float pz[4] = {a.z, b.y, c.x, c.w};

#pragma unroll
        for (int k = 0; k < 4; k++) {
            float x = px[k], y = py[k], z = pz[k];
            cd[4 * grp + k]  = (fabsf(x) < 0.5f) & (fabsf(y) < 0.5f) &
                               (fabsf(z) < 0.5f);
            idx[4 * grp + k] = (to_idx(x) * NB + to_idx(y)) * NB + to_idx(z);
        }
    }

    // ---- 8 predicated gathers, all in flight before any consumption ----
#pragma unroll
    for (int k = 0; k < 8; k++) {
        float4 g = make_float4(0.f, 0.f, 0.f, 0.f);
        if (cd[k]) g = __ldg(&vox[idx[k]]);   // predicated LDG.E.128
        v[k] = g;
    }

    // ---- epilogue: write results back into own smem slots ----
#pragma unroll
    for (int grp = 0; grp < 2; grp++) {
        const int g = tid + grp * TPB;
        float ro[12], dv[4];
#pragma unroll
        for (int k = 0; k < 4; k++) {
            const float4 w = v[4 * grp + k];
            ro[3 * k + 0] = fast_sigmoid(w.x);
            ro[3 * k + 1] = fast_sigmoid(w.y);
            ro[3 * k + 2] = fast_sigmoid(w.z);
            dv[k] = fmaxf(w.w * 10.0f, 0.0f);
        }
        s_buf[3 * g + 0] = make_float4(ro[0], ro[1], ro[2],  ro[3]);
        s_buf[3 * g + 1] = make_float4(ro[4], ro[5], ro[6],  ro[7]);
        s_buf[3 * g + 2] = make_float4(ro[8], ro[9], ro[10], ro[11]);
        s_dens[g]        = make_float4(dv[0], dv[1], dv[2],  dv[3]);
    }
    __syncthreads();

    // ---- TMA bulk stores (rgb 12 KB, dens 4 KB) ----
    if (tid == 0) {
        asm volatile("fence.proxy.async.shared::cta;" ::: "memory");
        asm volatile(
            "cp.async.bulk.global.shared::cta.bulk_group [%0], [%1], %2;"
            :: "l"(rgb_out + base * 3), "r"(smem_u32(s_buf)), "n"(X_BYTES)
            : "memory");
        asm volatile(
            "cp.async.bulk.global.shared::cta.bulk_group [%0], [%1], %2;"
            :: "l"(dens_out + base), "r"(smem_u32(s_dens)), "n"(D_BYTES)
            : "memory");
        asm volatile("cp.async.bulk.commit_group;" ::: "memory");
        asm volatile("cp.async.bulk.wait_group.read 0;" ::: "memory");
    }
}

extern "C" void kernel_launch(void* const* d_in, const int* in_sizes, int n_in,
                              void* d_out, int out_size)
{
    const float* X      = (const float*)d_in[0];   // [N,3]
    const float* voxels = (const float*)d_in[1];   // [128,128,128,4]

    int n = in_sizes[0] / 3;                       // 8388608
    int nblocks = n / PPB;                         // 8192

    float* out      = (float*)d_out;
    float* rgb_out  = out;                         // first 3N floats
    float* dens_out = out + 3LL * n;               // last  N floats

    voxels_kernel<<<nblocks, TPB>>>(
        X, (const float4*)voxels, rgb_out, dens_out);
}

// round 12
// speedup vs baseline: 1.8912x; 1.2257x over previous
#include <cuda_runtime.h>
#include <cstdint>

// Voxels_40518721470753 — R4 champion shell (grid 8192, TPB 256, 1024-pt tile,
// TMA in/out, branchless predicated gathers) + tanh sigmoid + .cg gathers.
// out[0:3N] = sigmoid(rgb) ([N,3]); out[3N:4N] = relu(dens*10)
// idx(v) = ((int)floorf(v*128+64) - 1) & 127 ; !cond -> rgb 0.5, dens 0

#define NB        128
#define TPB       256
#define PPB       1024                 // points per block
#define X_BYTES   (PPB * 3 * 4)        // 12288
#define D_BYTES   (PPB * 4)            // 4096

__device__ __forceinline__ uint32_t smem_u32(const void* p) {
    return (uint32_t)__cvta_generic_to_shared(p);
}
__device__ __forceinline__ float fast_sigmoid(float v) {
    // sigmoid(v) = 0.5*tanh(v/2) + 0.5  (1 MUFU; rel_err ~5e-7, validated R8/R9)
    float t, h = 0.5f * v;
    asm("tanh.approx.f32 %0, %1;" : "=f"(t) : "f"(h));
    return fmaf(0.5f, t, 0.5f);
}
__device__ __forceinline__ int to_idx(float v) {
    return (((int)floorf(v * 128.0f + 64.0f)) - 1) & (NB - 1);
}

__global__ __launch_bounds__(TPB) void voxels_kernel(
    const float*  __restrict__ Xg,        // [N,3]
    const float4* __restrict__ vox,       // [128^3] float4
    float*        __restrict__ rgb_out,   // 3N floats
    float*        __restrict__ dens_out)  // N floats
{
    __shared__ __align__(128) float4 s_buf[PPB * 3 / 4];  // 12 KB: X -> rgb
    __shared__ __align__(128) float4 s_dens[PPB / 4];     // 4 KB
    __shared__ __align__(8)   uint64_t mbar;

    const int tid = threadIdx.x;
    const long long base = (long long)blockIdx.x * PPB;

    const uint32_t mb = smem_u32(&mbar);
    if (tid == 0) {
        asm volatile("mbarrier.init.shared::cta.b64 [%0], 1;" :: "r"(mb) : "memory");
    }
    __syncthreads();

    // ---- TMA bulk load of this block's X tile ----
    if (tid == 0) {
        asm volatile("mbarrier.arrive.expect_tx.shared::cta.b64 _, [%0], %1;"
                     :: "r"(mb), "n"(X_BYTES) : "memory");
        asm volatile(
            "cp.async.bulk.shared::cluster.global.mbarrier::complete_tx::bytes "
            "[%0], [%1], %2, [%3];"
            :: "r"(smem_u32(s_buf)), "l"(Xg + base * 3), "n"(X_BYTES), "r"(mb)
            : "memory");
    }
    asm volatile(
        "{\n\t"
        ".reg .pred P;\n\t"
        "W%=:\n\t"
        "mbarrier.try_wait.parity.shared::cta.b64 P, [%0], 0, 10000000;\n\t"
        "@!P bra W%=;\n\t"
        "}"
        :: "r"(mb) : "memory");

    // ---- per-thread compute: points 4*tid .. 4*tid+3 ----
    // 48 B lane stride -> conflict-free LDS.128 within quarter-warp phases.
    float4 a = s_buf[3 * tid + 0];
    float4 b = s_buf[3 * tid + 1];
    float4 c = s_buf[3 * tid + 2];

    float px[4] = {a.x, a.w, b.z, c.y};
    float py[4] = {a.y, b.x, b.w, c.z};
    float pz[4] = {a.z, b.y, c.x, c.w};

    int  idx[4];
    bool cd[4];
#pragma unroll
    for (int k = 0; k < 4; k++) {
        float x = px[k], y = py[k], z = pz[k];
        cd[k]  = (fabsf(x) < 0.5f) & (fabsf(y) < 0.5f) & (fabsf(z) < 0.5f);
        idx[k] = (to_idx(x) * NB + to_idx(y)) * NB + to_idx(z);
    }

    // branchless predicated gathers, 4 in flight, L2-only (.cg): the 32 MB
    // table can't live in L1, so skip L1 allocation/tag churn entirely.
    float4 v[4];
#pragma unroll
    for (int k = 0; k < 4; k++) {
        float4 g = make_float4(0.f, 0.f, 0.f, 0.f);
        if (cd[k]) g = __ldcg(&vox[idx[k]]);   // predicated LDG.E.CG.128
        v[k] = g;
    }

    float ro[12], dv[4];
#pragma unroll
    for (int k = 0; k < 4; k++) {
        ro[3 * k + 0] = fast_sigmoid(v[k].x);
        ro[3 * k + 1] = fast_sigmoid(v[k].y);
        ro[3 * k + 2] = fast_sigmoid(v[k].z);
        dv[k] = fmaxf(v[k].w * 10.0f, 0.0f);
    }

    // write results back into own smem slots (no cross-thread hazard)
    s_buf[3 * tid + 0] = make_float4(ro[0], ro[1], ro[2],  ro[3]);
    s_buf[3 * tid + 1] = make_float4(ro[4], ro[5], ro[6],  ro[7]);
    s_buf[3 * tid + 2] = make_float4(ro[8], ro[9], ro[10], ro[11]);
    s_dens[tid]        = make_float4(dv[0], dv[1], dv[2],  dv[3]);
    __syncthreads();

    // ---- TMA bulk stores (rgb 12 KB, dens 4 KB) ----
    if (tid == 0) {
        asm volatile("fence.proxy.async.shared::cta;" ::: "memory");
        asm volatile(
            "cp.async.bulk.global.shared::cta.bulk_group [%0], [%1], %2;"
            :: "l"(rgb_out + base * 3), "r"(smem_u32(s_buf)), "n"(X_BYTES)
            : "memory");
        asm volatile(
            "cp.async.bulk.global.shared::cta.bulk_group [%0], [%1], %2;"
            :: "l"(dens_out + base), "r"(smem_u32(s_dens)), "n"(D_BYTES)
            : "memory");
        asm volatile("cp.async.bulk.commit_group;" ::: "memory");
        asm volatile("cp.async.bulk.wait_group.read 0;" ::: "memory");
    }
}

extern "C" void kernel_launch(void* const* d_in, const int* in_sizes, int n_in,
                              void* d_out, int out_size)
{
    const float* X      = (const float*)d_in[0];   // [N,3]
    const float* voxels = (const float*)d_in[1];   // [128,128,128,4]

    int n = in_sizes[0] / 3;                       // 8388608
    int nblocks = n / PPB;                         // 8192

    float* out      = (float*)d_out;
    float* rgb_out  = out;                         // first 3N floats
    float* dens_out = out + 3LL * n;               // last  N floats

    voxels_kernel<<<nblocks, TPB>>>(
        X, (const float4*)voxels, rgb_out, dens_out);
}